// round 1
// baseline (speedup 1.0000x reference)
#include <cuda_runtime.h>
#include <cfloat>

#define BB   4
#define NN   16384
#define MM   1024
#define CC   64
#define COP  64
#define COUT 128
#define KK   32
#define R2   0.25f

// Packed dual-FMA: d.lo = a.lo*b.lo + c.lo ; d.hi = a.hi*b.hi + c.hi
__device__ __forceinline__ float2 ffma2(float2 a, float2 b, float2 c) {
    float2 d;
    asm("{\n"
        ".reg .b64 ra, rb, rc, rd;\n"
        "mov.b64 ra, {%2, %3};\n"
        "mov.b64 rb, {%4, %5};\n"
        "mov.b64 rc, {%6, %7};\n"
        "fma.rn.f32x2 rd, ra, rb, rc;\n"
        "mov.b64 {%0, %1}, rd;\n"
        "}"
        : "=f"(d.x), "=f"(d.y)
        : "f"(a.x), "f"(a.y), "f"(b.x), "f"(b.y), "f"(c.x), "f"(c.y));
    return d;
}

__global__ __launch_bounds__(128)
void pointnet_sampler_kernel(
    const float* __restrict__ positions,   // (B, N, 3)
    const float* __restrict__ features,    // (B, N, 64)
    const float* __restrict__ centers,     // (B, M, 3)
    const float* __restrict__ distances,   // (B, M, N)
    const float* __restrict__ W_op,        // (67, 64)
    const float* __restrict__ b_op,        // (64)
    const float* __restrict__ W_agg,       // (64, 128)
    const float* __restrict__ b_agg,       // (128)
    float* __restrict__ out)               // (B, M, 128)
{
    const int blk  = blockIdx.x;          // b*M + m
    const int b    = blk >> 10;           // / MM
    const int m    = blk & (MM - 1);
    const int tid  = threadIdx.x;
    const int lane = tid & 31;
    const int wid  = tid >> 5;
    const int c    = tid & 63;            // c_op channel
    const int kg   = tid >> 6;            // k-group: 0 or 1

    __shared__ __align__(16) float s_in[KK][68];  // [rel3 | feat64 | pad0]
    __shared__ int   s_idx[KK];
    __shared__ int   s_V;
    __shared__ float s_part[2][COP];
    __shared__ float s_pool[COP];

    const float* drow = distances + ((size_t)b * MM + m) * NN;

    // ---- Phase A0: warp 0 prefetches 256 distances (MLP=8, one trip) ----
    float dv[8];
    if (wid == 0) {
#pragma unroll
        for (int j = 0; j < 8; j++) dv[j] = drow[j * 32 + lane];
    }

    // ---- all threads: W_op column -> registers, packed along i ----
    float2 w2[34];
#pragma unroll
    for (int i2 = 0; i2 < 33; i2++) {
        w2[i2].x = W_op[(2 * i2) * COP + c];
        w2[i2].y = W_op[(2 * i2 + 1) * COP + c];
    }
    w2[33].x = W_op[66 * COP + c];
    w2[33].y = 0.f;
    const float bop = b_op[c];

    // ---- Phase A1: ordered ball-query scan (warp 0) ----
    if (wid == 0) {
        int count = 0;
#pragma unroll
        for (int j = 0; j < 8; j++) {
            if (count < KK) {                  // warp-uniform
                bool v = dv[j] < R2;
                unsigned msk = __ballot_sync(0xffffffffu, v);
                int pre = __popc(msk & ((1u << lane) - 1u));
                if (v && count + pre < KK) s_idx[count + pre] = j * 32 + lane;
                count += __popc(msk);
            }
        }
        int base = 256;
        while (count < KK && base < NN) {      // rare fallback (~1% of rows)
            float d = drow[base + lane];
            bool v = d < R2;
            unsigned msk = __ballot_sync(0xffffffffu, v);
            int pre = __popc(msk & ((1u << lane) - 1u));
            if (v && count + pre < KK) s_idx[count + pre] = base + lane;
            count += __popc(msk);
            base += 32;
        }
        if (lane == 0) s_V = min(count, KK);
    }
    __syncthreads();
    const int V = s_V;

    // ---- Phase A2: gather neighbor inputs into shared ----
    const float* featb = features + (size_t)b * NN * CC;
    for (int t = tid; t < KK * CC; t += 128) {
        int k = t >> 6, i = t & 63;
        if (k < V) s_in[k][3 + i] = featb[(size_t)s_idx[k] * CC + i];
    }
    if (tid < KK * 3) {
        int k = tid / 3, d = tid - k * 3;
        if (k < V)
            s_in[k][d] = positions[((size_t)b * NN + s_idx[k]) * 3 + d]
                       - centers[((size_t)b * MM + m) * 3 + d];
    }
    if (tid < KK) s_in[tid][67] = 0.f;  // pad so packed i=67 term is 0
    __syncthreads();

    // ---- Phase B: neighbor operator + running max-pool ----
    float vmax = -FLT_MAX;
    const int k0 = kg * 16;
    const int kend = min(V, k0 + 16);       // warp-uniform
    for (int k = k0; k < kend; k++) {
        const float4* row4 = reinterpret_cast<const float4*>(s_in[k]);
        float2 a0 = make_float2(0.f, 0.f);
        float2 a1 = make_float2(0.f, 0.f);
#pragma unroll
        for (int q = 0; q < 17; q++) {
            float4 v = row4[q];             // broadcast LDS.128
            a0 = ffma2(make_float2(v.x, v.y), w2[2 * q],     a0);
            a1 = ffma2(make_float2(v.z, v.w), w2[2 * q + 1], a1);
        }
        float f = (a0.x + a0.y) + (a1.x + a1.y) + bop;
        vmax = fmaxf(vmax, f);
    }
    s_part[kg][c] = vmax;
    __syncthreads();

    if (tid < COP) {
        float mx = fmaxf(s_part[0][tid], s_part[1][tid]);
        // zero rows participate in the max only if some slot is invalid
        if (V < KK) mx = fmaxf(mx, 0.f);
        s_pool[tid] = mx;
    }
    __syncthreads();

    // ---- Phase C: aggregator linear (64 -> 128) + ReLU ----
    float acc = b_agg[tid];
#pragma unroll
    for (int cc = 0; cc < COP; cc++)
        acc = fmaf(s_pool[cc], W_agg[cc * COUT + tid], acc);
    out[(size_t)blk * COUT + tid] = fmaxf(acc, 0.f);
}

extern "C" void kernel_launch(void* const* d_in, const int* in_sizes, int n_in,
                              void* d_out, int out_size)
{
    (void)in_sizes; (void)n_in; (void)out_size;
    pointnet_sampler_kernel<<<BB * MM, 128>>>(
        (const float*)d_in[0],  // positions
        (const float*)d_in[1],  // features
        (const float*)d_in[2],  // centers
        (const float*)d_in[3],  // distances
        (const float*)d_in[4],  // W_op
        (const float*)d_in[5],  // b_op
        (const float*)d_in[6],  // W_agg
        (const float*)d_in[7],  // b_agg
        (float*)d_out);
}

// round 3
// speedup vs baseline: 1.1904x; 1.1904x over previous
#include <cuda_runtime.h>
#include <cfloat>

#define BB   4
#define NN   16384
#define MM   1024
#define CC   64
#define COP  64
#define COUT 128
#define KK   32
#define R2   0.25f
#define NI   67          // 3 rel + 64 feat
#define XTS  36          // X^T row stride in floats (144B, 16B-aligned)

// Packed dual-FMA on Blackwell: d = a*b + c per 32-bit lane.
__device__ __forceinline__ float2 ffma2(float2 a, float2 b, float2 c) {
    float2 d;
    asm("{\n"
        ".reg .b64 ra, rb, rc, rd;\n"
        "mov.b64 ra, {%2, %3};\n"
        "mov.b64 rb, {%4, %5};\n"
        "mov.b64 rc, {%6, %7};\n"
        "fma.rn.f32x2 rd, ra, rb, rc;\n"
        "mov.b64 {%0, %1}, rd;\n"
        "}"
        : "=f"(d.x), "=f"(d.y)
        : "f"(a.x), "f"(a.y), "f"(b.x), "f"(b.y), "f"(c.x), "f"(c.y));
    return d;
}

__global__ __launch_bounds__(128)
void pointnet_sampler_kernel(
    const float* __restrict__ positions,   // (B, N, 3)
    const float* __restrict__ features,    // (B, N, 64)
    const float* __restrict__ centers,     // (B, M, 3)
    const float* __restrict__ distances,   // (B, M, N)
    const float* __restrict__ W_op,        // (67, 64)
    const float* __restrict__ b_op,        // (64)
    const float* __restrict__ W_agg,       // (64, 128)
    const float* __restrict__ b_agg,       // (128)
    float* __restrict__ out)               // (B, M, 128)
{
    const int blk  = blockIdx.x;
    const int b    = blk >> 10;
    const int m    = blk & (MM - 1);
    const int tid  = threadIdx.x;
    const int lane = tid & 31;
    const int wid  = tid >> 5;
    const int kt   = tid & 7;     // k-tile: k in [4kt, 4kt+4)
    const int ct   = tid >> 3;    // c-tile: c in [4ct, 4ct+4)  (0..15)

    __shared__ __align__(16) float s_XT[NI][XTS];   // X^T: [i][k]
    __shared__ int   s_idx[KK];
    __shared__ int   s_V;
    __shared__ __align__(16) float s_pool[COP];

    const float* drow = distances + ((size_t)b * MM + m) * NN;

    // ---- Phase A0: warp 0 prefetches 256 distances (MLP=8) ----
    float dv[8];
    if (wid == 0) {
#pragma unroll
        for (int j = 0; j < 8; j++) dv[j] = drow[j * 32 + lane];
    }

    // ---- Phase A1: ordered ball-query (warp 0) ----
    if (wid == 0) {
        int count = 0;
#pragma unroll
        for (int j = 0; j < 8; j++) {
            if (count < KK) {
                bool v = dv[j] < R2;
                unsigned msk = __ballot_sync(0xffffffffu, v);
                int pre = __popc(msk & ((1u << lane) - 1u));
                if (v && count + pre < KK) s_idx[count + pre] = j * 32 + lane;
                count += __popc(msk);
            }
        }
        int base = 256;
        while (count < KK && base < NN) {     // rare fallback
            float d = drow[base + lane];
            bool v = d < R2;
            unsigned msk = __ballot_sync(0xffffffffu, v);
            int pre = __popc(msk & ((1u << lane) - 1u));
            if (v && count + pre < KK) s_idx[count + pre] = base + lane;
            count += __popc(msk);
            base += 32;
        }
        if (lane == 0) s_V = min(count, KK);
    }
    __syncthreads();
    const int V = s_V;

    // ---- Phase A2: gather into transposed smem X^T[i][k] ----
    {
        // rel-pos rows i = 0..2 (threads 0..31, one k each)
        if (tid < KK && tid < V) {
            int id = s_idx[tid];
            const float* pp = positions + ((size_t)b * NN + id) * 3;
            const float* cp = centers   + ((size_t)b * MM + m)  * 3;
            s_XT[0][tid] = pp[0] - cp[0];
            s_XT[1][tid] = pp[1] - cp[1];
            s_XT[2][tid] = pp[2] - cp[2];
        }
        // feature rows: thread handles k = tid&31, i-chunk ic = tid>>5 (16 i's)
        int k  = tid & 31;
        int ic = tid >> 5;
        if (k < V) {
            const float4* fr = reinterpret_cast<const float4*>(
                features + ((size_t)b * NN + s_idx[k]) * CC + ic * 16);
            float4 v0 = fr[0], v1 = fr[1], v2 = fr[2], v3 = fr[3];
            int r = 3 + ic * 16;
            s_XT[r + 0][k]  = v0.x; s_XT[r + 1][k]  = v0.y;
            s_XT[r + 2][k]  = v0.z; s_XT[r + 3][k]  = v0.w;
            s_XT[r + 4][k]  = v1.x; s_XT[r + 5][k]  = v1.y;
            s_XT[r + 6][k]  = v1.z; s_XT[r + 7][k]  = v1.w;
            s_XT[r + 8][k]  = v2.x; s_XT[r + 9][k]  = v2.y;
            s_XT[r + 10][k] = v2.z; s_XT[r + 11][k] = v2.w;
            s_XT[r + 12][k] = v3.x; s_XT[r + 13][k] = v3.y;
            s_XT[r + 14][k] = v3.z; s_XT[r + 15][k] = v3.w;
        }
    }
    __syncthreads();

    // ---- Phase B: register-tiled GEMM  F(32x64) = X(32x67) * W(67x64) ----
    float2 a0[4], a1[4];          // a0[cc]=(k0,k1), a1[cc]=(k2,k3) for channel 4ct+cc
#pragma unroll
    for (int cc = 0; cc < 4; cc++) {
        a0[cc] = make_float2(0.f, 0.f);
        a1[cc] = make_float2(0.f, 0.f);
    }
    const float* Xp = &s_XT[0][4 * kt];
    const float* Wp = W_op + 4 * ct;
#pragma unroll 4
    for (int i = 0; i < NI; i++) {
        float4 xf = *reinterpret_cast<const float4*>(Xp + i * XTS);
        float4 wf = __ldg(reinterpret_cast<const float4*>(Wp + i * COP));
        float2 x01 = make_float2(xf.x, xf.y);
        float2 x23 = make_float2(xf.z, xf.w);
        a0[0] = ffma2(x01, make_float2(wf.x, wf.x), a0[0]);
        a1[0] = ffma2(x23, make_float2(wf.x, wf.x), a1[0]);
        a0[1] = ffma2(x01, make_float2(wf.y, wf.y), a0[1]);
        a1[1] = ffma2(x23, make_float2(wf.y, wf.y), a1[1]);
        a0[2] = ffma2(x01, make_float2(wf.z, wf.z), a0[2]);
        a1[2] = ffma2(x23, make_float2(wf.z, wf.z), a1[2]);
        a0[3] = ffma2(x01, make_float2(wf.w, wf.w), a0[3]);
        a1[3] = ffma2(x23, make_float2(wf.w, wf.w), a1[3]);
    }

    // ---- bias + masked max over this thread's 4 k's ----
    float4 bo = __ldg(reinterpret_cast<const float4*>(b_op + 4 * ct));
    const float bv[4] = {bo.x, bo.y, bo.z, bo.w};
    const int kb = 4 * kt;
    float tm[4];
#pragma unroll
    for (int cc = 0; cc < 4; cc++) {
        float mx = -FLT_MAX;
        if (kb + 0 < V) mx = fmaxf(mx, a0[cc].x + bv[cc]);
        if (kb + 1 < V) mx = fmaxf(mx, a0[cc].y + bv[cc]);
        if (kb + 2 < V) mx = fmaxf(mx, a1[cc].x + bv[cc]);
        if (kb + 3 < V) mx = fmaxf(mx, a1[cc].y + bv[cc]);
        tm[cc] = mx;
    }
    // reduce over kt (8 consecutive lanes share a ct) via butterfly shuffles
#pragma unroll
    for (int d = 1; d < 8; d <<= 1) {
#pragma unroll
        for (int cc = 0; cc < 4; cc++)
            tm[cc] = fmaxf(tm[cc], __shfl_xor_sync(0xffffffffu, tm[cc], d));
    }
    if (kt == 0) {
        float z = (V < KK) ? 0.f : -FLT_MAX;   // zero row joins max iff a slot invalid
        *reinterpret_cast<float4*>(&s_pool[4 * ct]) =
            make_float4(fmaxf(tm[0], z), fmaxf(tm[1], z),
                        fmaxf(tm[2], z), fmaxf(tm[3], z));
    }
    __syncthreads();

    // ---- Phase C: aggregator linear (64 -> 128) + ReLU ----
    float acc = b_agg[tid];
    const float4* p4 = reinterpret_cast<const float4*>(s_pool);
#pragma unroll
    for (int q = 0; q < 16; q++) {
        float4 p = p4[q];
        acc = fmaf(p.x, __ldg(&W_agg[(4 * q + 0) * COUT + tid]), acc);
        acc = fmaf(p.y, __ldg(&W_agg[(4 * q + 1) * COUT + tid]), acc);
        acc = fmaf(p.z, __ldg(&W_agg[(4 * q + 2) * COUT + tid]), acc);
        acc = fmaf(p.w, __ldg(&W_agg[(4 * q + 3) * COUT + tid]), acc);
    }
    out[(size_t)blk * COUT + tid] = fmaxf(acc, 0.f);
}

extern "C" void kernel_launch(void* const* d_in, const int* in_sizes, int n_in,
                              void* d_out, int out_size)
{
    (void)in_sizes; (void)n_in; (void)out_size;
    pointnet_sampler_kernel<<<BB * MM, 128>>>(
        (const float*)d_in[0],  // positions
        (const float*)d_in[1],  // features
        (const float*)d_in[2],  // centers
        (const float*)d_in[3],  // distances
        (const float*)d_in[4],  // W_op
        (const float*)d_in[5],  // b_op
        (const float*)d_in[6],  // W_agg
        (const float*)d_in[7],  // b_agg
        (float*)d_out);
}

// round 4
// speedup vs baseline: 1.4703x; 1.2352x over previous
#include <cuda_runtime.h>
#include <cfloat>

#define BB   4
#define NN   16384
#define MM   1024
#define CC   64
#define COP  64
#define COUT 128
#define KK   32
#define R2   0.25f
#define NI   67          // 3 rel + 64 feat
#define XTS  36          // X^T row stride (floats), 16B-aligned rows
#define SRS  68          // staging row stride (floats), 16B-aligned
#define G    2           // centers per CTA

// Packed dual-FMA on Blackwell: d = a*b + c per 32-bit lane.
__device__ __forceinline__ float2 ffma2(float2 a, float2 b, float2 c) {
    float2 d;
    asm("{\n"
        ".reg .b64 ra, rb, rc, rd;\n"
        "mov.b64 ra, {%2, %3};\n"
        "mov.b64 rb, {%4, %5};\n"
        "mov.b64 rc, {%6, %7};\n"
        "fma.rn.f32x2 rd, ra, rb, rc;\n"
        "mov.b64 {%0, %1}, rd;\n"
        "}"
        : "=f"(d.x), "=f"(d.y)
        : "f"(a.x), "f"(a.y), "f"(b.x), "f"(b.y), "f"(c.x), "f"(c.y));
    return d;
}

__global__ __launch_bounds__(128)
void pointnet_sampler_kernel(
    const float* __restrict__ positions,   // (B, N, 3)
    const float* __restrict__ features,    // (B, N, 64)
    const float* __restrict__ centers,     // (B, M, 3)
    const float* __restrict__ distances,   // (B, M, N)
    const float* __restrict__ W_op,        // (67, 64)
    const float* __restrict__ b_op,        // (64)
    const float* __restrict__ W_agg,       // (64, 128)
    const float* __restrict__ b_agg,       // (128)
    float* __restrict__ out)               // (B, M, 128)
{
    const int blk  = blockIdx.x;          // 0..2047
    const int b    = blk >> 9;
    const int m0   = (blk & 511) * G;     // first center of the pair
    const int tid  = threadIdx.x;
    const int lane = tid & 31;
    const int wid  = tid >> 5;
    const int kt   = tid & 7;             // k-tile: k in [4kt, 4kt+4)
    const int ct   = tid >> 3;            // c-tile: c in [4ct, 4ct+4)

    __shared__ __align__(16) float s_stage[KK][SRS];     // row-major gather staging
    __shared__ __align__(16) float s_XT[G][NI][XTS];     // X^T per center
    __shared__ int   s_idx[G][KK];
    __shared__ int   s_V[G];
    __shared__ __align__(16) float s_pool[G][COP];

    // ---- Phase A: ball query, warps 0 and 1 handle one center each ----
    if (wid < G) {
        const float* drow = distances + ((size_t)b * MM + m0 + wid) * NN;
        float dv[8];
#pragma unroll
        for (int j = 0; j < 8; j++) dv[j] = drow[j * 32 + lane];
        int count = 0;
#pragma unroll
        for (int j = 0; j < 8; j++) {
            if (count < KK) {
                bool v = dv[j] < R2;
                unsigned msk = __ballot_sync(0xffffffffu, v);
                int pre = __popc(msk & ((1u << lane) - 1u));
                if (v && count + pre < KK) s_idx[wid][count + pre] = j * 32 + lane;
                count += __popc(msk);
            }
        }
        int base = 256;
        while (count < KK && base < NN) {    // rare fallback
            float d = drow[base + lane];
            bool v = d < R2;
            unsigned msk = __ballot_sync(0xffffffffu, v);
            int pre = __popc(msk & ((1u << lane) - 1u));
            if (v && count + pre < KK) s_idx[wid][count + pre] = base + lane;
            count += __popc(msk);
            base += 32;
        }
        if (lane == 0) s_V[wid] = min(count, KK);
    }
    __syncthreads();

    const float* featb = features + (size_t)b * NN * CC;

    // rel-pos rows (i=0..2) for both centers: threads 0..63
    if (tid < G * KK) {
        int g = tid >> 5, k = tid & 31;
        if (k < s_V[g]) {
            int id = s_idx[g][k];
            const float* pp = positions + ((size_t)b * NN + id) * 3;
            const float* cp = centers   + ((size_t)b * MM + m0 + g) * 3;
            s_XT[g][0][k] = pp[0] - cp[0];
            s_XT[g][1][k] = pp[1] - cp[1];
            s_XT[g][2][k] = pp[2] - cp[2];
        }
    }

    // ---- gather + transpose, per center (staging buffer reused) ----
#pragma unroll
    for (int g = 0; g < G; g++) {
        const int V = s_V[g];
        // coalesced load: chunk cid = tid + 128*j ; row k = cid>>4, 16B chunk c16 = cid&15
        // 16 consecutive lanes cover one full 256B feature row -> 4 lines per inst
        float4 v[4];
#pragma unroll
        for (int j = 0; j < 4; j++) {
            int cid = tid + 128 * j;
            int k = cid >> 4, c16 = cid & 15;
            int id = (k < V) ? s_idx[g][k] : 0;    // safe row for invalid slots
            v[j] = *reinterpret_cast<const float4*>(featb + (size_t)id * CC + c16 * 4);
        }
        if (g) __syncthreads();                     // prior transpose done reading stage
#pragma unroll
        for (int j = 0; j < 4; j++) {
            int cid = tid + 128 * j;
            int k = cid >> 4, c16 = cid & 15;
            *reinterpret_cast<float4*>(&s_stage[k][c16 * 4]) = v[j];
        }
        __syncthreads();
        // transpose: thread (k=lane, warp w) reads chunks {w, w+4, w+8, w+12}
        {
            int k = lane;
#pragma unroll
            for (int t = 0; t < 4; t++) {
                int c = wid + 4 * t;                 // uniform per warp-inst
                float4 x = *reinterpret_cast<const float4*>(&s_stage[k][c * 4]);
                int r = 3 + 4 * c;
                s_XT[g][r + 0][k] = x.x;             // lanes: distinct k -> conflict-free
                s_XT[g][r + 1][k] = x.y;
                s_XT[g][r + 2][k] = x.z;
                s_XT[g][r + 3][k] = x.w;
            }
        }
    }
    __syncthreads();
    const int V0 = s_V[0], V1 = s_V[1];

    // ---- Phase B: register-tiled GEMMs, W fragment shared by both centers ----
    float2 a0[G][4], a1[G][4];
#pragma unroll
    for (int g = 0; g < G; g++)
#pragma unroll
        for (int cc = 0; cc < 4; cc++) {
            a0[g][cc] = make_float2(0.f, 0.f);
            a1[g][cc] = make_float2(0.f, 0.f);
        }
    const float* Wp = W_op + 4 * ct;
#pragma unroll 4
    for (int i = 0; i < NI; i++) {
        float4 wf = __ldg(reinterpret_cast<const float4*>(Wp + i * COP));
#pragma unroll
        for (int g = 0; g < G; g++) {
            float4 xf = *reinterpret_cast<const float4*>(&s_XT[g][i][4 * kt]);
            float2 x01 = make_float2(xf.x, xf.y);
            float2 x23 = make_float2(xf.z, xf.w);
            a0[g][0] = ffma2(x01, make_float2(wf.x, wf.x), a0[g][0]);
            a1[g][0] = ffma2(x23, make_float2(wf.x, wf.x), a1[g][0]);
            a0[g][1] = ffma2(x01, make_float2(wf.y, wf.y), a0[g][1]);
            a1[g][1] = ffma2(x23, make_float2(wf.y, wf.y), a1[g][1]);
            a0[g][2] = ffma2(x01, make_float2(wf.z, wf.z), a0[g][2]);
            a1[g][2] = ffma2(x23, make_float2(wf.z, wf.z), a1[g][2]);
            a0[g][3] = ffma2(x01, make_float2(wf.w, wf.w), a0[g][3]);
            a1[g][3] = ffma2(x23, make_float2(wf.w, wf.w), a1[g][3]);
        }
    }

    // ---- bias + masked max over this thread's 4 k's, per center ----
    float4 bo = __ldg(reinterpret_cast<const float4*>(b_op + 4 * ct));
    const float bv[4] = {bo.x, bo.y, bo.z, bo.w};
    const int kb = 4 * kt;
#pragma unroll
    for (int g = 0; g < G; g++) {
        const int V = g ? V1 : V0;
        float tm[4];
#pragma unroll
        for (int cc = 0; cc < 4; cc++) {
            float mx = -FLT_MAX;
            if (kb + 0 < V) mx = fmaxf(mx, a0[g][cc].x + bv[cc]);
            if (kb + 1 < V) mx = fmaxf(mx, a0[g][cc].y + bv[cc]);
            if (kb + 2 < V) mx = fmaxf(mx, a1[g][cc].x + bv[cc]);
            if (kb + 3 < V) mx = fmaxf(mx, a1[g][cc].y + bv[cc]);
            tm[cc] = mx;
        }
#pragma unroll
        for (int d = 1; d < 8; d <<= 1)
#pragma unroll
            for (int cc = 0; cc < 4; cc++)
                tm[cc] = fmaxf(tm[cc], __shfl_xor_sync(0xffffffffu, tm[cc], d));
        if (kt == 0) {
            float z = (V < KK) ? 0.f : -FLT_MAX;
            *reinterpret_cast<float4*>(&s_pool[g][4 * ct]) =
                make_float4(fmaxf(tm[0], z), fmaxf(tm[1], z),
                            fmaxf(tm[2], z), fmaxf(tm[3], z));
        }
    }
    __syncthreads();

    // ---- Phase C: aggregator (64 -> 128) + ReLU; W_agg shared by both centers ----
    float accA = b_agg[tid], accB = accA;
    const float4* p40 = reinterpret_cast<const float4*>(s_pool[0]);
    const float4* p41 = reinterpret_cast<const float4*>(s_pool[1]);
#pragma unroll
    for (int q = 0; q < 16; q++) {
        float4 pA = p40[q];
        float4 pB = p41[q];
        float w0 = __ldg(&W_agg[(4 * q + 0) * COUT + tid]);
        float w1 = __ldg(&W_agg[(4 * q + 1) * COUT + tid]);
        float w2 = __ldg(&W_agg[(4 * q + 2) * COUT + tid]);
        float w3 = __ldg(&W_agg[(4 * q + 3) * COUT + tid]);
        accA = fmaf(pA.x, w0, accA); accB = fmaf(pB.x, w0, accB);
        accA = fmaf(pA.y, w1, accA); accB = fmaf(pB.y, w1, accB);
        accA = fmaf(pA.z, w2, accA); accB = fmaf(pB.z, w2, accB);
        accA = fmaf(pA.w, w3, accA); accB = fmaf(pB.w, w3, accB);
    }
    size_t obase = ((size_t)b * MM + m0) * COUT + tid;
    out[obase]        = fmaxf(accA, 0.f);
    out[obase + COUT] = fmaxf(accB, 0.f);
}

extern "C" void kernel_launch(void* const* d_in, const int* in_sizes, int n_in,
                              void* d_out, int out_size)
{
    (void)in_sizes; (void)n_in; (void)out_size;
    pointnet_sampler_kernel<<<BB * MM / G, 128>>>(
        (const float*)d_in[0],  // positions
        (const float*)d_in[1],  // features
        (const float*)d_in[2],  // centers
        (const float*)d_in[3],  // distances
        (const float*)d_in[4],  // W_op
        (const float*)d_in[5],  // b_op
        (const float*)d_in[6],  // W_agg
        (const float*)d_in[7],  // b_agg
        (float*)d_out);
}